// round 4
// baseline (speedup 1.0000x reference)
#include <cuda_runtime.h>
#include <cstdint>

// Problem constants
#define NN 4096
#define FF 128
#define HID 128
#define HEADS 8
#define HDIM 16
#define CC 64
#define EE 131072

// ---------------- scratch (no allocation allowed) ----------------
__device__ float g_H[NN * HID];     // raw X@W (pre-scatter), conv1/conv2 reuse
__device__ float g_G[NN * HID];     // conv1 accum target / conv2 input
__device__ float g_G2[NN * HID];    // conv2 accum target
__device__ float g_QKV[NN * 3 * FF];
__device__ float g_O[NN * FF];      // attention output
__device__ float g_TF[NN * FF];     // after out_proj
__device__ float g_GNN[NN * CC];    // gnn branch output
__device__ float g_deg[NN];
__device__ float g_dinv[NN];

// ---------------- helpers ----------------
__device__ __forceinline__ unsigned cvt_tf32(float f) {
    unsigned u; asm("cvt.rna.tf32.f32 %0, %1;" : "=r"(u) : "f"(f)); return u;
}
__device__ __forceinline__ unsigned f16x2_hl(float hi, float lo) {
    unsigned u; asm("cvt.rn.f16x2.f32 %0, %1, %2;" : "=r"(u) : "f"(hi), "f"(lo)); return u;
}
__device__ __forceinline__ void mma_tf32(float c[4], const unsigned a[4],
                                         unsigned b0, unsigned b1) {
    asm("mma.sync.aligned.m16n8k8.row.col.f32.tf32.tf32.f32 "
        "{%0,%1,%2,%3}, {%4,%5,%6,%7}, {%8,%9}, {%0,%1,%2,%3};"
        : "+f"(c[0]), "+f"(c[1]), "+f"(c[2]), "+f"(c[3])
        : "r"(a[0]), "r"(a[1]), "r"(a[2]), "r"(a[3]), "r"(b0), "r"(b1));
}
__device__ __forceinline__ void mma_f16(float c[4], unsigned a0, unsigned a1,
                                        unsigned a2, unsigned a3,
                                        unsigned b0, unsigned b1) {
    asm("mma.sync.aligned.m16n8k16.row.col.f32.f16.f16.f32 "
        "{%0,%1,%2,%3}, {%4,%5,%6,%7}, {%8,%9}, {%0,%1,%2,%3};"
        : "+f"(c[0]), "+f"(c[1]), "+f"(c[2]), "+f"(c[3])
        : "r"(a0), "r"(a1), "r"(a2), "r"(a3), "r"(b0), "r"(b1));
}

// ---------------- small elementwise kernels ----------------
__global__ void deg_init_kernel(float* deg) {
    int i = blockIdx.x * blockDim.x + threadIdx.x;
    if (i < NN) deg[i] = 1.0f;   // self loop
}
__global__ void deg_count_kernel(const int* col, float* deg) {
    int e = blockIdx.x * blockDim.x + threadIdx.x;
    if (e < EE) atomicAdd(&deg[col[e]], 1.0f);
}
__global__ void dinv_kernel(const float* deg, float* dinv) {
    int i = blockIdx.x * blockDim.x + threadIdx.x;
    if (i < NN) dinv[i] = rsqrtf(deg[i]);
}

// ---------------- edge scatter: out[col] += H[row] * dinv[row]*dinv[col] ----
__global__ void scatter_kernel(const float* __restrict__ H,
                               const int* __restrict__ row,
                               const int* __restrict__ col,
                               const float* __restrict__ dinv,
                               float* __restrict__ out) {
    int gid = blockIdx.x * blockDim.x + threadIdx.x;
    int e = gid >> 5;
    if (e >= EE) return;
    int lane = gid & 31;
    int r = row[e];
    int c = col[e];
    float w = dinv[r] * dinv[c];
    float4 hv = *(const float4*)(H + r * HID + lane * 4);
    float* dst = out + c * HID + lane * 4;
    asm volatile("red.global.add.v4.f32 [%0], {%1, %2, %3, %4};"
                 :: "l"(dst), "f"(hv.x * w), "f"(hv.y * w), "f"(hv.z * w), "f"(hv.w * w)
                 : "memory");
}

// ---------------- tf32 tensor-core GEMM ----------------
// C[M,N] = op(A)[M,K] @ B, tiles 64x64x32, 8 warps (4x2), warp tile 16x32.
// TRANSB: B is [N,K] (weight.T). RELU_A: relu applied to A on load.
// SELF: dual output — Hout=raw acc, C = bias + acc*dinv[r]^2 (GCN self-loop).
// DO_ADD/DO_RELU: final-projection epilogue. bias always valid.
// Requires M%64==0, N%64==0, K%32==0.
template <bool TRANSB, bool RELU_A, bool SELF, bool DO_ADD, bool DO_RELU>
__global__ __launch_bounds__(256)
void tgemm_kernel(const float* __restrict__ A, const float* __restrict__ B,
                  const float* __restrict__ bias, const float* __restrict__ add,
                  const float* __restrict__ dinv,
                  float* __restrict__ C, float* __restrict__ Hout,
                  int M, int N, int K) {
    __shared__ unsigned As[64][36];   // pad 36: frag bank = 4g+t -> conflict-free
    __shared__ unsigned Bs[32][72];   // pad 72: frag bank = 8t+g -> conflict-free

    const int tid  = threadIdx.x;
    const int warp = tid >> 5;
    const int lane = tid & 31;
    const int g = lane >> 2;
    const int t = lane & 3;
    const int wm = warp >> 1;         // 0..3
    const int wn = warp & 1;          // 0..1
    const int m0 = blockIdx.y * 64;
    const int n0 = blockIdx.x * 64;

    float acc[4][4];
    #pragma unroll
    for (int nf = 0; nf < 4; nf++)
        #pragma unroll
        for (int i = 0; i < 4; i++) acc[nf][i] = 0.0f;

    for (int k0 = 0; k0 < K; k0 += 32) {
        // fill A: 64x32, 8 floats/thread
        {
            int ar = tid >> 2;            // 0..63
            int ac = (tid & 3) * 8;       // 0,8,16,24
            #pragma unroll
            for (int i = 0; i < 2; i++) {
                float4 v = *(const float4*)(A + (m0 + ar) * K + k0 + ac + i * 4);
                if (RELU_A) {
                    v.x = fmaxf(v.x, 0.0f); v.y = fmaxf(v.y, 0.0f);
                    v.z = fmaxf(v.z, 0.0f); v.w = fmaxf(v.w, 0.0f);
                }
                As[ar][ac + i * 4 + 0] = cvt_tf32(v.x);
                As[ar][ac + i * 4 + 1] = cvt_tf32(v.y);
                As[ar][ac + i * 4 + 2] = cvt_tf32(v.z);
                As[ar][ac + i * 4 + 3] = cvt_tf32(v.w);
            }
        }
        // fill B: Bs[k][n], 32x64
        if (!TRANSB) {
            int br = tid >> 3;            // 0..31
            int bc = (tid & 7) * 8;       // 0..56
            #pragma unroll
            for (int i = 0; i < 2; i++) {
                float4 v = *(const float4*)(B + (k0 + br) * N + n0 + bc + i * 4);
                Bs[br][bc + i * 4 + 0] = cvt_tf32(v.x);
                Bs[br][bc + i * 4 + 1] = cvt_tf32(v.y);
                Bs[br][bc + i * 4 + 2] = cvt_tf32(v.z);
                Bs[br][bc + i * 4 + 3] = cvt_tf32(v.w);
            }
        } else {
            int bn = tid >> 2;            // 0..63
            int bk = (tid & 3) * 8;       // 0,8,16,24
            #pragma unroll
            for (int i = 0; i < 2; i++) {
                float4 v = *(const float4*)(B + (n0 + bn) * K + k0 + bk + i * 4);
                Bs[bk + i * 4 + 0][bn] = cvt_tf32(v.x);
                Bs[bk + i * 4 + 1][bn] = cvt_tf32(v.y);
                Bs[bk + i * 4 + 2][bn] = cvt_tf32(v.z);
                Bs[bk + i * 4 + 3][bn] = cvt_tf32(v.w);
            }
        }
        __syncthreads();

        #pragma unroll
        for (int ks = 0; ks < 4; ks++) {
            unsigned a[4];
            int mr = wm * 16;
            a[0] = As[mr + g][ks * 8 + t];
            a[1] = As[mr + g + 8][ks * 8 + t];
            a[2] = As[mr + g][ks * 8 + t + 4];
            a[3] = As[mr + g + 8][ks * 8 + t + 4];
            #pragma unroll
            for (int nf = 0; nf < 4; nf++) {
                int nc = wn * 32 + nf * 8 + g;
                unsigned b0 = Bs[ks * 8 + t][nc];
                unsigned b1 = Bs[ks * 8 + t + 4][nc];
                mma_tf32(acc[nf], a, b0, b1);
            }
        }
        __syncthreads();
    }

    // epilogue
    const int r0 = m0 + wm * 16 + g;
    const int r1 = r0 + 8;
    #pragma unroll
    for (int nf = 0; nf < 4; nf++) {
        int c = n0 + wn * 32 + nf * 8 + 2 * t;
        float2 v0 = make_float2(acc[nf][0], acc[nf][1]);
        float2 v1 = make_float2(acc[nf][2], acc[nf][3]);
        float bx = bias[c], by = bias[c + 1];
        if (SELF) {
            *(float2*)(Hout + r0 * N + c) = v0;
            *(float2*)(Hout + r1 * N + c) = v1;
            float d0 = dinv[r0]; d0 *= d0;
            float d1 = dinv[r1]; d1 *= d1;
            v0 = make_float2(bx + v0.x * d0, by + v0.y * d0);
            v1 = make_float2(bx + v1.x * d1, by + v1.y * d1);
        } else {
            v0.x += bx; v0.y += by;
            v1.x += bx; v1.y += by;
            if (DO_ADD) {
                float2 a0 = *(const float2*)(add + r0 * N + c);
                float2 a1 = *(const float2*)(add + r1 * N + c);
                v0.x += a0.x; v0.y += a0.y;
                v1.x += a1.x; v1.y += a1.y;
            }
            if (DO_RELU) {
                v0.x = fmaxf(v0.x, 0.0f); v0.y = fmaxf(v0.y, 0.0f);
                v1.x = fmaxf(v1.x, 0.0f); v1.y = fmaxf(v1.y, 0.0f);
            }
        }
        *(float2*)(C + r0 * N + c) = v0;
        *(float2*)(C + r1 * N + c) = v1;
    }
}

// ---------------- tensor-core flash attention (round-3, unchanged) ----------
__global__ __launch_bounds__(256)
void attn_mma_kernel(const float* __restrict__ QKV, float* __restrict__ O) {
    const int h    = blockIdx.y;
    const int warp = threadIdx.x >> 5;
    const int lane = threadIdx.x & 31;
    const int g    = lane >> 2;
    const int t    = lane & 3;
    const int q0   = blockIdx.x * 128 + warp * 16;

    __shared__ unsigned Ks[64][17];
    __shared__ float    Vs[64][17];

    const float qscale = 0.25f * 1.4426950408889634f;

    unsigned qa[2][4];
    {
        const float* Qb = QKV + h * HDIM;
        #pragma unroll
        for (int kk = 0; kk < 2; kk++) {
            qa[kk][0] = cvt_tf32(Qb[(q0 + g)     * 384 + kk * 8 + t]     * qscale);
            qa[kk][1] = cvt_tf32(Qb[(q0 + g + 8) * 384 + kk * 8 + t]     * qscale);
            qa[kk][2] = cvt_tf32(Qb[(q0 + g)     * 384 + kk * 8 + t + 4] * qscale);
            qa[kk][3] = cvt_tf32(Qb[(q0 + g + 8) * 384 + kk * 8 + t + 4] * qscale);
        }
    }

    float o[2][4];
    #pragma unroll
    for (int dt = 0; dt < 2; dt++)
        #pragma unroll
        for (int i = 0; i < 4; i++) o[dt][i] = 0.0f;
    float l0 = 0.0f, l1 = 0.0f;

    for (int k0 = 0; k0 < NN; k0 += 64) {
        __syncthreads();
        {
            int key = threadIdx.x & 63;
            int dh  = (threadIdx.x >> 6) * 4;
            const float* kb = QKV + (k0 + key) * 384 + FF + h * HDIM + dh;
            float4 kv = *(const float4*)kb;
            float4 vv = *(const float4*)(kb + FF);
            Ks[key][dh + 0] = cvt_tf32(kv.x);
            Ks[key][dh + 1] = cvt_tf32(kv.y);
            Ks[key][dh + 2] = cvt_tf32(kv.z);
            Ks[key][dh + 3] = cvt_tf32(kv.w);
            Vs[key][dh + 0] = vv.x;
            Vs[key][dh + 1] = vv.y;
            Vs[key][dh + 2] = vv.z;
            Vs[key][dh + 3] = vv.w;
        }
        __syncthreads();

        float c[8][4];
        #pragma unroll
        for (int j = 0; j < 8; j++) {
            c[j][0] = c[j][1] = c[j][2] = c[j][3] = 0.0f;
            #pragma unroll
            for (int kk = 0; kk < 2; kk++) {
                unsigned b0 = Ks[j * 8 + g][kk * 8 + t];
                unsigned b1 = Ks[j * 8 + g][kk * 8 + t + 4];
                mma_tf32(c[j], qa[kk], b0, b1);
            }
        }

        #pragma unroll
        for (int j = 0; j < 8; j++) {
            c[j][0] = exp2f(c[j][0] - 8.0f);
            c[j][1] = exp2f(c[j][1] - 8.0f);
            c[j][2] = exp2f(c[j][2] - 8.0f);
            c[j][3] = exp2f(c[j][3] - 8.0f);
            l0 += c[j][0] + c[j][1];
            l1 += c[j][2] + c[j][3];
        }

        #pragma unroll
        for (int kt = 0; kt < 4; kt++) {
            unsigned a0 = f16x2_hl(c[2 * kt][1],     c[2 * kt][0]);
            unsigned a1 = f16x2_hl(c[2 * kt][3],     c[2 * kt][2]);
            unsigned a2 = f16x2_hl(c[2 * kt + 1][1], c[2 * kt + 1][0]);
            unsigned a3 = f16x2_hl(c[2 * kt + 1][3], c[2 * kt + 1][2]);
            int kb = kt * 16;
            #pragma unroll
            for (int dt = 0; dt < 2; dt++) {
                int d = dt * 8 + g;
                unsigned b0 = f16x2_hl(Vs[kb + 2 * t + 1][d], Vs[kb + 2 * t][d]);
                unsigned b1 = f16x2_hl(Vs[kb + 2 * t + 9][d], Vs[kb + 2 * t + 8][d]);
                mma_f16(o[dt], a0, a1, a2, a3, b0, b1);
            }
        }
    }

    l0 += __shfl_xor_sync(0xffffffffu, l0, 1);
    l0 += __shfl_xor_sync(0xffffffffu, l0, 2);
    l1 += __shfl_xor_sync(0xffffffffu, l1, 1);
    l1 += __shfl_xor_sync(0xffffffffu, l1, 2);
    float inv0 = 1.0f / l0;
    float inv1 = 1.0f / l1;

    #pragma unroll
    for (int dt = 0; dt < 2; dt++) {
        int col = h * HDIM + dt * 8 + 2 * t;
        float2 v0 = make_float2(o[dt][0] * inv0, o[dt][1] * inv0);
        float2 v1 = make_float2(o[dt][2] * inv1, o[dt][3] * inv1);
        *(float2*)(O + (q0 + g)     * FF + col) = v0;
        *(float2*)(O + (q0 + g + 8) * FF + col) = v1;
    }
}

// ---------------- launch ----------------
extern "C" void kernel_launch(void* const* d_in, const int* in_sizes, int n_in,
                              void* d_out, int out_size) {
    const float* x          = (const float*)d_in[0];
    const int*   edge_index = (const int*)  d_in[1];
    const float* W1         = (const float*)d_in[2];
    const float* b1         = (const float*)d_in[3];
    const float* W2         = (const float*)d_in[4];
    const float* b2         = (const float*)d_in[5];
    const float* W3         = (const float*)d_in[6];
    const float* b3         = (const float*)d_in[7];
    const float* in_w       = (const float*)d_in[8];
    const float* in_b       = (const float*)d_in[9];
    const float* out_w      = (const float*)d_in[10];
    const float* out_b      = (const float*)d_in[11];
    const float* proj_w     = (const float*)d_in[12];
    const float* proj_b     = (const float*)d_in[13];
    float* out = (float*)d_out;

    const int* row = edge_index;
    const int* col = edge_index + EE;

    float *H, *G, *G2, *QKV, *O, *TF, *GNN, *deg, *dinv;
    cudaGetSymbolAddress((void**)&H,   g_H);
    cudaGetSymbolAddress((void**)&G,   g_G);
    cudaGetSymbolAddress((void**)&G2,  g_G2);
    cudaGetSymbolAddress((void**)&QKV, g_QKV);
    cudaGetSymbolAddress((void**)&O,   g_O);
    cudaGetSymbolAddress((void**)&TF,  g_TF);
    cudaGetSymbolAddress((void**)&GNN, g_GNN);
    cudaGetSymbolAddress((void**)&deg, g_deg);
    cudaGetSymbolAddress((void**)&dinv,g_dinv);

    // degree / normalization
    deg_init_kernel<<<(NN + 255) / 256, 256>>>(deg);
    deg_count_kernel<<<(EE + 255) / 256, 256>>>(col, deg);
    dinv_kernel<<<(NN + 255) / 256, 256>>>(deg, dinv);

    // ---- GCN conv 1: H = x@W1 ; G = b1 + H*dinv^2 ; G += scatter(H) ----
    tgemm_kernel<false, false, true, false, false>
        <<<dim3(HID / 64, NN / 64), 256>>>(x, W1, b1, nullptr, dinv, G, H, NN, HID, FF);
    scatter_kernel<<<(EE * 32 + 255) / 256, 256>>>(H, row, col, dinv, G);

    // ---- GCN conv 2: H = relu(G)@W2 ; G2 = b2 + H*dinv^2 ; G2 += scatter(H) ----
    tgemm_kernel<false, true, true, false, false>
        <<<dim3(HID / 64, NN / 64), 256>>>(G, W2, b2, nullptr, dinv, G2, H, NN, HID, HID);
    scatter_kernel<<<(EE * 32 + 255) / 256, 256>>>(H, row, col, dinv, G2);

    // ---- GNN head: GNN = relu(G2)@W3 + b3 ----
    tgemm_kernel<false, true, false, false, false>
        <<<dim3(CC / 64, NN / 64), 256>>>(G2, W3, b3, nullptr, nullptr, GNN, nullptr, NN, CC, HID);

    // ---- Transformer branch ----
    tgemm_kernel<true, false, false, false, false>
        <<<dim3(3 * FF / 64, NN / 64), 256>>>(x, in_w, in_b, nullptr, nullptr, QKV, nullptr, NN, 3 * FF, FF);
    attn_mma_kernel<<<dim3(NN / 128, HEADS), 256>>>(QKV, O);
    tgemm_kernel<true, false, false, false, false>
        <<<dim3(FF / 64, NN / 64), 256>>>(O, out_w, out_b, nullptr, nullptr, TF, nullptr, NN, FF, FF);
    // out = relu(TF @ proj_w + proj_b + GNN)
    tgemm_kernel<false, false, false, true, true>
        <<<dim3(CC / 64, NN / 64), 256>>>(TF, proj_w, proj_b, GNN, nullptr, out, nullptr, NN, CC, FF);
}

// round 5
// speedup vs baseline: 1.3925x; 1.3925x over previous
#include <cuda_runtime.h>
#include <cstdint>

// Problem constants
#define NN 4096
#define FF 128
#define HID 128
#define HEADS 8
#define HDIM 16
#define CC 64
#define EE 131072

// ---------------- scratch (no allocation allowed) ----------------
__device__ float g_H[NN * HID];     // GEMM output of X@W (pre-gather)
__device__ float g_G[NN * HID];     // conv1 output (post-relu)
__device__ float g_G2[NN * HID];    // conv2 output (post-relu)
__device__ float g_QKV[NN * 3 * FF];
__device__ float g_O[NN * FF];      // attention output
__device__ float g_TF[NN * FF];     // after out_proj
__device__ float g_GNN[NN * CC];    // gnn branch output
__device__ float g_dinv[NN];
__device__ int   g_count[NN];       // in-degree (excl. self)
__device__ int   g_off[NN + 1];     // CSR offsets by destination
__device__ int   g_cur[NN];         // fill cursors
__device__ int   g_srow[EE];        // source rows sorted by destination

// ---------------- CSR build kernels ----------------
__global__ void zero_count_kernel(int* count) {
    int i = blockIdx.x * blockDim.x + threadIdx.x;
    if (i < NN) count[i] = 0;
}

__global__ void hist_kernel(const int* __restrict__ col, int* __restrict__ count) {
    int e = blockIdx.x * blockDim.x + threadIdx.x;
    if (e < EE) atomicAdd(&count[col[e]], 1);
}

// single block, 1024 threads, 4 elements each: exclusive scan of count[4096]
__global__ __launch_bounds__(1024)
void scan_kernel(const int* __restrict__ count, int* __restrict__ off,
                 int* __restrict__ cur) {
    __shared__ int wsum[32];
    int t = threadIdx.x;
    int lane = t & 31, warp = t >> 5;
    int base = t * 4;
    int v0 = count[base + 0], v1 = count[base + 1];
    int v2 = count[base + 2], v3 = count[base + 3];
    int s = v0 + v1 + v2 + v3;
    int x = s;
    #pragma unroll
    for (int d = 1; d < 32; d <<= 1) {
        int y = __shfl_up_sync(0xffffffffu, x, d);
        if (lane >= d) x += y;
    }
    if (lane == 31) wsum[warp] = x;
    __syncthreads();
    if (warp == 0) {
        int w = wsum[lane];
        #pragma unroll
        for (int d = 1; d < 32; d <<= 1) {
            int y = __shfl_up_sync(0xffffffffu, w, d);
            if (lane >= d) w += y;
        }
        wsum[lane] = w;
    }
    __syncthreads();
    int run = x - s + (warp ? wsum[warp - 1] : 0);
    off[base + 0] = run; cur[base + 0] = run; run += v0;
    off[base + 1] = run; cur[base + 1] = run; run += v1;
    off[base + 2] = run; cur[base + 2] = run; run += v2;
    off[base + 3] = run; cur[base + 3] = run; run += v3;
    if (t == 1023) off[NN] = run;
}

__global__ void dinv_kernel(const int* __restrict__ count, float* __restrict__ dinv) {
    int i = blockIdx.x * blockDim.x + threadIdx.x;
    if (i < NN) dinv[i] = rsqrtf(1.0f + (float)count[i]);
}

__global__ void reorder_kernel(const int* __restrict__ row, const int* __restrict__ col,
                               int* __restrict__ cur, int* __restrict__ srow) {
    int e = blockIdx.x * blockDim.x + threadIdx.x;
    if (e >= EE) return;
    int pos = atomicAdd(&cur[col[e]], 1);
    srow[pos] = row[e];
}

// ---------------- segmented gather (replaces atomic scatter) ----------------
// out[c] = relu( bias + dinv[c] * ( dinv[c]*H[c] + sum_{r in N(c)} dinv[r]*H[r] ) )
// one warp per destination node; each lane owns 4 floats (float4).
__global__ __launch_bounds__(256)
void gather_kernel(const float* __restrict__ H,
                   const int* __restrict__ srow, const int* __restrict__ off,
                   const float* __restrict__ dinv, const float* __restrict__ bias,
                   float* __restrict__ out) {
    int warp = threadIdx.x >> 5;
    int lane = threadIdx.x & 31;
    int c = blockIdx.x * 8 + warp;
    int d = lane * 4;

    float dc = dinv[c];
    float4 hs = *(const float4*)(H + c * HID + d);
    float4 acc = make_float4(dc * hs.x, dc * hs.y, dc * hs.z, dc * hs.w);

    int i = off[c];
    int e_ = off[c + 1];
    for (; i + 4 <= e_; i += 4) {
        int r0 = srow[i], r1 = srow[i + 1], r2 = srow[i + 2], r3 = srow[i + 3];
        float w0 = dinv[r0], w1 = dinv[r1], w2 = dinv[r2], w3 = dinv[r3];
        float4 h0 = *(const float4*)(H + r0 * HID + d);
        float4 h1 = *(const float4*)(H + r1 * HID + d);
        float4 h2 = *(const float4*)(H + r2 * HID + d);
        float4 h3 = *(const float4*)(H + r3 * HID + d);
        acc.x += w0 * h0.x + w1 * h1.x + w2 * h2.x + w3 * h3.x;
        acc.y += w0 * h0.y + w1 * h1.y + w2 * h2.y + w3 * h3.y;
        acc.z += w0 * h0.z + w1 * h1.z + w2 * h2.z + w3 * h3.z;
        acc.w += w0 * h0.w + w1 * h1.w + w2 * h2.w + w3 * h3.w;
    }
    for (; i < e_; i++) {
        int r = srow[i];
        float w = dinv[r];
        float4 h = *(const float4*)(H + r * HID + d);
        acc.x += w * h.x; acc.y += w * h.y; acc.z += w * h.z; acc.w += w * h.w;
    }

    float4 b = *(const float4*)(bias + d);
    float4 v;
    v.x = fmaxf(b.x + dc * acc.x, 0.0f);
    v.y = fmaxf(b.y + dc * acc.y, 0.0f);
    v.z = fmaxf(b.z + dc * acc.z, 0.0f);
    v.w = fmaxf(b.w + dc * acc.w, 0.0f);
    *(float4*)(out + c * HID + d) = v;
}

// ---------------- tiled SGEMM (scalar fp32, round-3 version) ----------------
template <bool TRANSB>
__global__ __launch_bounds__(256)
void sgemm_kernel(const float* __restrict__ A, const float* __restrict__ B,
                  const float* __restrict__ bias, const float* __restrict__ add,
                  float* __restrict__ C, int M, int N, int K, int do_relu) {
    const int BM = 64, BN = 64, BK = 16;
    __shared__ float As[BK][BM];
    __shared__ float Bs[BK][BN];

    int tid = threadIdx.x;
    int tx = tid & 15;
    int ty = tid >> 4;
    int m0 = blockIdx.y * BM;
    int n0 = blockIdx.x * BN;

    float acc[4][4];
    #pragma unroll
    for (int i = 0; i < 4; i++)
        #pragma unroll
        for (int j = 0; j < 4; j++) acc[i][j] = 0.0f;

    for (int k0 = 0; k0 < K; k0 += BK) {
        {
            int arow = tid >> 2;
            int acol = (tid & 3) * 4;
            float4 a = *(const float4*)(A + (m0 + arow) * K + k0 + acol);
            As[acol + 0][arow] = a.x;
            As[acol + 1][arow] = a.y;
            As[acol + 2][arow] = a.z;
            As[acol + 3][arow] = a.w;
        }
        if (!TRANSB) {
            int brow = tid >> 4;
            int bcol = (tid & 15) * 4;
            float4 b = *(const float4*)(B + (k0 + brow) * N + n0 + bcol);
            *(float4*)&Bs[brow][bcol] = b;
        } else {
            int bn = tid >> 2;
            int bk = (tid & 3) * 4;
            float4 b = *(const float4*)(B + (n0 + bn) * K + k0 + bk);
            Bs[bk + 0][bn] = b.x;
            Bs[bk + 1][bn] = b.y;
            Bs[bk + 2][bn] = b.z;
            Bs[bk + 3][bn] = b.w;
        }
        __syncthreads();

        #pragma unroll
        for (int kk = 0; kk < BK; kk++) {
            float4 av = *(const float4*)&As[kk][ty * 4];
            float4 bv = *(const float4*)&Bs[kk][tx * 4];
            float a[4] = {av.x, av.y, av.z, av.w};
            float b[4] = {bv.x, bv.y, bv.z, bv.w};
            #pragma unroll
            for (int i = 0; i < 4; i++)
                #pragma unroll
                for (int j = 0; j < 4; j++)
                    acc[i][j] += a[i] * b[j];
        }
        __syncthreads();
    }

    #pragma unroll
    for (int i = 0; i < 4; i++) {
        int r = m0 + ty * 4 + i;
        int cbase = n0 + tx * 4;
        float4 v;
        float* vp = &v.x;
        #pragma unroll
        for (int j = 0; j < 4; j++) {
            float x = acc[i][j];
            if (bias) x += bias[cbase + j];
            if (add)  x += add[r * N + cbase + j];
            if (do_relu) x = fmaxf(x, 0.0f);
            vp[j] = x;
        }
        *(float4*)(C + r * N + cbase) = v;
    }
}

// ---------------- tensor-core flash attention (round-3, unchanged) ----------
__device__ __forceinline__ unsigned cvt_tf32(float f) {
    unsigned u; asm("cvt.rna.tf32.f32 %0, %1;" : "=r"(u) : "f"(f)); return u;
}
__device__ __forceinline__ unsigned f16x2_hl(float hi, float lo) {
    unsigned u; asm("cvt.rn.f16x2.f32 %0, %1, %2;" : "=r"(u) : "f"(hi), "f"(lo)); return u;
}
__device__ __forceinline__ void mma_tf32(float c[4], const unsigned a[4],
                                         unsigned b0, unsigned b1) {
    asm("mma.sync.aligned.m16n8k8.row.col.f32.tf32.tf32.f32 "
        "{%0,%1,%2,%3}, {%4,%5,%6,%7}, {%8,%9}, {%0,%1,%2,%3};"
        : "+f"(c[0]), "+f"(c[1]), "+f"(c[2]), "+f"(c[3])
        : "r"(a[0]), "r"(a[1]), "r"(a[2]), "r"(a[3]), "r"(b0), "r"(b1));
}
__device__ __forceinline__ void mma_f16(float c[4], unsigned a0, unsigned a1,
                                        unsigned a2, unsigned a3,
                                        unsigned b0, unsigned b1) {
    asm("mma.sync.aligned.m16n8k16.row.col.f32.f16.f16.f32 "
        "{%0,%1,%2,%3}, {%4,%5,%6,%7}, {%8,%9}, {%0,%1,%2,%3};"
        : "+f"(c[0]), "+f"(c[1]), "+f"(c[2]), "+f"(c[3])
        : "r"(a0), "r"(a1), "r"(a2), "r"(a3), "r"(b0), "r"(b1));
}

__global__ __launch_bounds__(256)
void attn_mma_kernel(const float* __restrict__ QKV, float* __restrict__ O) {
    const int h    = blockIdx.y;
    const int warp = threadIdx.x >> 5;
    const int lane = threadIdx.x & 31;
    const int g    = lane >> 2;
    const int t    = lane & 3;
    const int q0   = blockIdx.x * 128 + warp * 16;

    __shared__ unsigned Ks[64][17];
    __shared__ float    Vs[64][17];

    const float qscale = 0.25f * 1.4426950408889634f;

    unsigned qa[2][4];
    {
        const float* Qb = QKV + h * HDIM;
        #pragma unroll
        for (int kk = 0; kk < 2; kk++) {
            qa[kk][0] = cvt_tf32(Qb[(q0 + g)     * 384 + kk * 8 + t]     * qscale);
            qa[kk][1] = cvt_tf32(Qb[(q0 + g + 8) * 384 + kk * 8 + t]     * qscale);
            qa[kk][2] = cvt_tf32(Qb[(q0 + g)     * 384 + kk * 8 + t + 4] * qscale);
            qa[kk][3] = cvt_tf32(Qb[(q0 + g + 8) * 384 + kk * 8 + t + 4] * qscale);
        }
    }

    float o[2][4];
    #pragma unroll
    for (int dt = 0; dt < 2; dt++)
        #pragma unroll
        for (int i = 0; i < 4; i++) o[dt][i] = 0.0f;
    float l0 = 0.0f, l1 = 0.0f;

    for (int k0 = 0; k0 < NN; k0 += 64) {
        __syncthreads();
        {
            int key = threadIdx.x & 63;
            int dh  = (threadIdx.x >> 6) * 4;
            const float* kb = QKV + (k0 + key) * 384 + FF + h * HDIM + dh;
            float4 kv = *(const float4*)kb;
            float4 vv = *(const float4*)(kb + FF);
            Ks[key][dh + 0] = cvt_tf32(kv.x);
            Ks[key][dh + 1] = cvt_tf32(kv.y);
            Ks[key][dh + 2] = cvt_tf32(kv.z);
            Ks[key][dh + 3] = cvt_tf32(kv.w);
            Vs[key][dh + 0] = vv.x;
            Vs[key][dh + 1] = vv.y;
            Vs[key][dh + 2] = vv.z;
            Vs[key][dh + 3] = vv.w;
        }
        __syncthreads();

        float c[8][4];
        #pragma unroll
        for (int j = 0; j < 8; j++) {
            c[j][0] = c[j][1] = c[j][2] = c[j][3] = 0.0f;
            #pragma unroll
            for (int kk = 0; kk < 2; kk++) {
                unsigned b0 = Ks[j * 8 + g][kk * 8 + t];
                unsigned b1 = Ks[j * 8 + g][kk * 8 + t + 4];
                mma_tf32(c[j], qa[kk], b0, b1);
            }
        }

        #pragma unroll
        for (int j = 0; j < 8; j++) {
            c[j][0] = exp2f(c[j][0] - 8.0f);
            c[j][1] = exp2f(c[j][1] - 8.0f);
            c[j][2] = exp2f(c[j][2] - 8.0f);
            c[j][3] = exp2f(c[j][3] - 8.0f);
            l0 += c[j][0] + c[j][1];
            l1 += c[j][2] + c[j][3];
        }

        #pragma unroll
        for (int kt = 0; kt < 4; kt++) {
            unsigned a0 = f16x2_hl(c[2 * kt][1],     c[2 * kt][0]);
            unsigned a1 = f16x2_hl(c[2 * kt][3],     c[2 * kt][2]);
            unsigned a2 = f16x2_hl(c[2 * kt + 1][1], c[2 * kt + 1][0]);
            unsigned a3 = f16x2_hl(c[2 * kt + 1][3], c[2 * kt + 1][2]);
            int kb = kt * 16;
            #pragma unroll
            for (int dt = 0; dt < 2; dt++) {
                int d = dt * 8 + g;
                unsigned b0 = f16x2_hl(Vs[kb + 2 * t + 1][d], Vs[kb + 2 * t][d]);
                unsigned b1 = f16x2_hl(Vs[kb + 2 * t + 9][d], Vs[kb + 2 * t + 8][d]);
                mma_f16(o[dt], a0, a1, a2, a3, b0, b1);
            }
        }
    }

    l0 += __shfl_xor_sync(0xffffffffu, l0, 1);
    l0 += __shfl_xor_sync(0xffffffffu, l0, 2);
    l1 += __shfl_xor_sync(0xffffffffu, l1, 1);
    l1 += __shfl_xor_sync(0xffffffffu, l1, 2);
    float inv0 = 1.0f / l0;
    float inv1 = 1.0f / l1;

    #pragma unroll
    for (int dt = 0; dt < 2; dt++) {
        int col = h * HDIM + dt * 8 + 2 * t;
        float2 v0 = make_float2(o[dt][0] * inv0, o[dt][1] * inv0);
        float2 v1 = make_float2(o[dt][2] * inv1, o[dt][3] * inv1);
        *(float2*)(O + (q0 + g)     * FF + col) = v0;
        *(float2*)(O + (q0 + g + 8) * FF + col) = v1;
    }
}

// ---------------- launch ----------------
extern "C" void kernel_launch(void* const* d_in, const int* in_sizes, int n_in,
                              void* d_out, int out_size) {
    const float* x          = (const float*)d_in[0];
    const int*   edge_index = (const int*)  d_in[1];
    const float* W1         = (const float*)d_in[2];
    const float* b1         = (const float*)d_in[3];
    const float* W2         = (const float*)d_in[4];
    const float* b2         = (const float*)d_in[5];
    const float* W3         = (const float*)d_in[6];
    const float* b3         = (const float*)d_in[7];
    const float* in_w       = (const float*)d_in[8];
    const float* in_b       = (const float*)d_in[9];
    const float* out_w      = (const float*)d_in[10];
    const float* out_b      = (const float*)d_in[11];
    const float* proj_w     = (const float*)d_in[12];
    const float* proj_b     = (const float*)d_in[13];
    float* out = (float*)d_out;

    const int* row = edge_index;
    const int* col = edge_index + EE;

    float *H, *G, *G2, *QKV, *O, *TF, *GNN, *dinv;
    int *cnt, *off, *cur, *srow;
    cudaGetSymbolAddress((void**)&H,    g_H);
    cudaGetSymbolAddress((void**)&G,    g_G);
    cudaGetSymbolAddress((void**)&G2,   g_G2);
    cudaGetSymbolAddress((void**)&QKV,  g_QKV);
    cudaGetSymbolAddress((void**)&O,    g_O);
    cudaGetSymbolAddress((void**)&TF,   g_TF);
    cudaGetSymbolAddress((void**)&GNN,  g_GNN);
    cudaGetSymbolAddress((void**)&dinv, g_dinv);
    cudaGetSymbolAddress((void**)&cnt,  g_count);
    cudaGetSymbolAddress((void**)&off,  g_off);
    cudaGetSymbolAddress((void**)&cur,  g_cur);
    cudaGetSymbolAddress((void**)&srow, g_srow);

    // ---- CSR build (per-launch, deterministic inputs) ----
    zero_count_kernel<<<(NN + 255) / 256, 256>>>(cnt);
    hist_kernel<<<(EE + 255) / 256, 256>>>(col, cnt);
    scan_kernel<<<1, 1024>>>(cnt, off, cur);
    dinv_kernel<<<(NN + 255) / 256, 256>>>(cnt, dinv);
    reorder_kernel<<<(EE + 255) / 256, 256>>>(row, col, cur, srow);

    // ---- GCN conv 1: H = x@W1 ; G = relu(gather) ----
    sgemm_kernel<false><<<dim3(HID / 64, NN / 64), 256>>>(x, W1, nullptr, nullptr, H, NN, HID, FF, 0);
    gather_kernel<<<NN / 8, 256>>>(H, srow, off, dinv, b1, G);

    // ---- GCN conv 2: H = G@W2 ; G2 = relu(gather) ----
    sgemm_kernel<false><<<dim3(HID / 64, NN / 64), 256>>>(G, W2, nullptr, nullptr, H, NN, HID, HID, 0);
    gather_kernel<<<NN / 8, 256>>>(H, srow, off, dinv, b2, G2);

    // ---- GNN head: GNN = G2 @ W3 + b3 ----
    sgemm_kernel<false><<<dim3(CC / 64, NN / 64), 256>>>(G2, W3, b3, nullptr, GNN, NN, CC, HID, 0);

    // ---- Transformer branch ----
    sgemm_kernel<true><<<dim3(3 * FF / 64, NN / 64), 256>>>(x, in_w, in_b, nullptr, QKV, NN, 3 * FF, FF, 0);
    attn_mma_kernel<<<dim3(NN / 128, HEADS), 256>>>(QKV, O);
    sgemm_kernel<true><<<dim3(FF / 64, NN / 64), 256>>>(O, out_w, out_b, nullptr, TF, NN, FF, FF, 0);
    // out = relu(TF @ proj_w + proj_b + GNN)
    sgemm_kernel<false><<<dim3(CC / 64, NN / 64), 256>>>(TF, proj_w, proj_b, GNN, out, NN, CC, FF, 1);
}

// round 6
// speedup vs baseline: 1.4414x; 1.0351x over previous
#include <cuda_runtime.h>
#include <cstdint>

// Problem constants
#define NN 4096
#define FF 128
#define HID 128
#define HEADS 8
#define HDIM 16
#define CC 64
#define EE 131072

// ---------------- scratch (no allocation allowed) ----------------
__device__ float g_H[NN * HID];     // GEMM output of X@W (pre-gather)
__device__ float g_G[NN * HID];     // conv1 output (post-relu)
__device__ float g_G2[NN * HID];    // conv2 output (post-relu)
__device__ float g_QKV[NN * 3 * FF];
__device__ float g_O[NN * FF];      // attention output
__device__ float g_TF[NN * FF];     // after out_proj
__device__ float g_GNN[NN * CC];    // gnn branch output
__device__ float g_dinv[NN];
__device__ int   g_count[NN];       // in-degree (excl. self)
__device__ int   g_off[NN + 1];     // CSR offsets by destination
__device__ int   g_cur[NN];         // fill cursors
__device__ int   g_srow[EE];        // source rows sorted by destination

// ---------------- CSR build kernels ----------------
__global__ void zero_count_kernel(int* count) {
    int i = blockIdx.x * blockDim.x + threadIdx.x;
    if (i < NN) count[i] = 0;
}

__global__ void hist_kernel(const int* __restrict__ col, int* __restrict__ count) {
    int e = blockIdx.x * blockDim.x + threadIdx.x;
    if (e < EE) atomicAdd(&count[col[e]], 1);
}

// single block, 1024 threads, 4 elements each: exclusive scan + dinv
__global__ __launch_bounds__(1024)
void scan_kernel(const int* __restrict__ count, int* __restrict__ off,
                 int* __restrict__ cur, float* __restrict__ dinv) {
    __shared__ int wsum[32];
    int t = threadIdx.x;
    int lane = t & 31, warp = t >> 5;
    int base = t * 4;
    int v0 = count[base + 0], v1 = count[base + 1];
    int v2 = count[base + 2], v3 = count[base + 3];
    dinv[base + 0] = rsqrtf(1.0f + (float)v0);
    dinv[base + 1] = rsqrtf(1.0f + (float)v1);
    dinv[base + 2] = rsqrtf(1.0f + (float)v2);
    dinv[base + 3] = rsqrtf(1.0f + (float)v3);
    int s = v0 + v1 + v2 + v3;
    int x = s;
    #pragma unroll
    for (int d = 1; d < 32; d <<= 1) {
        int y = __shfl_up_sync(0xffffffffu, x, d);
        if (lane >= d) x += y;
    }
    if (lane == 31) wsum[warp] = x;
    __syncthreads();
    if (warp == 0) {
        int w = wsum[lane];
        #pragma unroll
        for (int d = 1; d < 32; d <<= 1) {
            int y = __shfl_up_sync(0xffffffffu, w, d);
            if (lane >= d) w += y;
        }
        wsum[lane] = w;
    }
    __syncthreads();
    int run = x - s + (warp ? wsum[warp - 1] : 0);
    off[base + 0] = run; cur[base + 0] = run; run += v0;
    off[base + 1] = run; cur[base + 1] = run; run += v1;
    off[base + 2] = run; cur[base + 2] = run; run += v2;
    off[base + 3] = run; cur[base + 3] = run; run += v3;
    if (t == 1023) off[NN] = run;
}

__global__ void reorder_kernel(const int* __restrict__ row, const int* __restrict__ col,
                               int* __restrict__ cur, int* __restrict__ srow) {
    int e = blockIdx.x * blockDim.x + threadIdx.x;
    if (e >= EE) return;
    int pos = atomicAdd(&cur[col[e]], 1);
    srow[pos] = row[e];
}

// ---------------- segmented gather ----------------
// out[c] = relu( bias + dinv[c] * ( dinv[c]*H[c] + sum_{r in N(c)} dinv[r]*H[r] ) )
__global__ __launch_bounds__(256)
void gather_kernel(const float* __restrict__ H,
                   const int* __restrict__ srow, const int* __restrict__ off,
                   const float* __restrict__ dinv, const float* __restrict__ bias,
                   float* __restrict__ out) {
    int warp = threadIdx.x >> 5;
    int lane = threadIdx.x & 31;
    int c = blockIdx.x * 8 + warp;
    int d = lane * 4;

    float dc = dinv[c];
    float4 hs = *(const float4*)(H + c * HID + d);
    float4 acc = make_float4(dc * hs.x, dc * hs.y, dc * hs.z, dc * hs.w);

    int i = off[c];
    int e_ = off[c + 1];
    for (; i + 4 <= e_; i += 4) {
        int r0 = srow[i], r1 = srow[i + 1], r2 = srow[i + 2], r3 = srow[i + 3];
        float w0 = dinv[r0], w1 = dinv[r1], w2 = dinv[r2], w3 = dinv[r3];
        float4 h0 = *(const float4*)(H + r0 * HID + d);
        float4 h1 = *(const float4*)(H + r1 * HID + d);
        float4 h2 = *(const float4*)(H + r2 * HID + d);
        float4 h3 = *(const float4*)(H + r3 * HID + d);
        acc.x += w0 * h0.x + w1 * h1.x + w2 * h2.x + w3 * h3.x;
        acc.y += w0 * h0.y + w1 * h1.y + w2 * h2.y + w3 * h3.y;
        acc.z += w0 * h0.z + w1 * h1.z + w2 * h2.z + w3 * h3.z;
        acc.w += w0 * h0.w + w1 * h1.w + w2 * h2.w + w3 * h3.w;
    }
    for (; i < e_; i++) {
        int r = srow[i];
        float w = dinv[r];
        float4 h = *(const float4*)(H + r * HID + d);
        acc.x += w * h.x; acc.y += w * h.y; acc.z += w * h.z; acc.w += w * h.w;
    }

    float4 b = *(const float4*)(bias + d);
    float4 v;
    v.x = fmaxf(b.x + dc * acc.x, 0.0f);
    v.y = fmaxf(b.y + dc * acc.y, 0.0f);
    v.z = fmaxf(b.z + dc * acc.z, 0.0f);
    v.w = fmaxf(b.w + dc * acc.w, 0.0f);
    *(float4*)(out + c * HID + d) = v;
}

// ---------------- software-pipelined SGEMM ----------------
// C[M,N] = A[M,K] @ B (+bias)(+add)(relu); double-buffered smem,
// register prefetch of next K-tile, one __syncthreads per iteration.
// BK=32. Requires M%BM==0, N%BN==0, K%32==0.
template <int BM, int BN, bool TRANSB, bool HAS_BIAS, bool DO_ADD, bool DO_RELU>
__global__ __launch_bounds__(256)
void pgemm_kernel(const float* __restrict__ A, const float* __restrict__ B,
                  const float* __restrict__ bias, const float* __restrict__ add,
                  float* __restrict__ C, int M, int N, int K) {
    constexpr int NA = BM / 32;      // float4 loads per thread for A tile
    constexpr int NB = BN / 32;      // float4 loads per thread for B tile
    constexpr int RM = BM / 16;
    constexpr int RN = BN / 16;
    __shared__ float As[2][32][BM + 4];   // transposed: As[k][m]
    __shared__ float Bs[2][32][BN];       // Bs[k][n]

    const int tid = threadIdx.x;
    const int tx = tid & 15, ty = tid >> 4;
    const int m0 = blockIdx.y * BM, n0 = blockIdx.x * BN;

    float4 pa[NA], pb[NB];

    auto loadA = [&](int k0) {
        #pragma unroll
        for (int i = 0; i < NA; i++) {
            int fl = tid + i * 256;
            int ar = fl >> 3, ac = (fl & 7) * 4;
            pa[i] = *(const float4*)(A + (m0 + ar) * K + k0 + ac);
        }
    };
    auto storeA = [&](int buf) {
        #pragma unroll
        for (int i = 0; i < NA; i++) {
            int fl = tid + i * 256;
            int ar = fl >> 3, ac = (fl & 7) * 4;
            As[buf][ac + 0][ar] = pa[i].x;
            As[buf][ac + 1][ar] = pa[i].y;
            As[buf][ac + 2][ar] = pa[i].z;
            As[buf][ac + 3][ar] = pa[i].w;
        }
    };
    auto loadB = [&](int k0) {
        #pragma unroll
        for (int i = 0; i < NB; i++) {
            int fl = tid + i * 256;
            if (!TRANSB) {
                int br = fl / (BN / 4), bc = (fl % (BN / 4)) * 4;
                pb[i] = *(const float4*)(B + (k0 + br) * N + n0 + bc);
            } else {
                int bn = fl >> 3, bk = (fl & 7) * 4;
                pb[i] = *(const float4*)(B + (n0 + bn) * K + k0 + bk);
            }
        }
    };
    auto storeB = [&](int buf) {
        #pragma unroll
        for (int i = 0; i < NB; i++) {
            int fl = tid + i * 256;
            if (!TRANSB) {
                int br = fl / (BN / 4), bc = (fl % (BN / 4)) * 4;
                *(float4*)&Bs[buf][br][bc] = pb[i];
            } else {
                int bn = fl >> 3, bk = (fl & 7) * 4;
                Bs[buf][bk + 0][bn] = pb[i].x;
                Bs[buf][bk + 1][bn] = pb[i].y;
                Bs[buf][bk + 2][bn] = pb[i].z;
                Bs[buf][bk + 3][bn] = pb[i].w;
            }
        }
    };

    loadA(0); loadB(0);
    storeA(0); storeB(0);
    __syncthreads();

    float acc[RM][RN];
    #pragma unroll
    for (int i = 0; i < RM; i++)
        #pragma unroll
        for (int j = 0; j < RN; j++) acc[i][j] = 0.0f;

    const int nit = K >> 5;
    for (int it = 0; it < nit; it++) {
        const int cur = it & 1;
        if (it + 1 < nit) { loadA((it + 1) * 32); loadB((it + 1) * 32); }

        #pragma unroll
        for (int kk = 0; kk < 32; kk++) {
            float a[RM], b[RN];
            if (RM == 4) {
                float4 av = *(const float4*)&As[cur][kk][ty * 4];
                a[0] = av.x; a[1] = av.y; a[2] = av.z; a[3] = av.w;
            } else {
                float2 av = *(const float2*)&As[cur][kk][ty * 2];
                a[0] = av.x; a[1] = av.y;
            }
            if (RN == 4) {
                float4 bv = *(const float4*)&Bs[cur][kk][tx * 4];
                b[0] = bv.x; b[1] = bv.y; b[2] = bv.z; b[3] = bv.w;
            } else {
                float2 bv = *(const float2*)&Bs[cur][kk][tx * 2];
                b[0] = bv.x; b[1] = bv.y;
            }
            #pragma unroll
            for (int i = 0; i < RM; i++)
                #pragma unroll
                for (int j = 0; j < RN; j++)
                    acc[i][j] += a[i] * b[j];
        }

        if (it + 1 < nit) {
            storeA((it + 1) & 1); storeB((it + 1) & 1);
            __syncthreads();
        }
    }

    // epilogue
    #pragma unroll
    for (int i = 0; i < RM; i++) {
        int r = m0 + ty * RM + i;
        #pragma unroll
        for (int j = 0; j < RN; j++) {
            int c = n0 + tx * RN + j;
            float v = acc[i][j];
            if (HAS_BIAS) v += bias[c];
            if (DO_ADD)  v += add[r * N + c];
            if (DO_RELU) v = fmaxf(v, 0.0f);
            C[r * N + c] = v;
        }
    }
}

// ---------------- tensor-core flash attention ----------------
__device__ __forceinline__ unsigned cvt_tf32(float f) {
    unsigned u; asm("cvt.rna.tf32.f32 %0, %1;" : "=r"(u) : "f"(f)); return u;
}
__device__ __forceinline__ unsigned f16x2_hl(float hi, float lo) {
    unsigned u; asm("cvt.rn.f16x2.f32 %0, %1, %2;" : "=r"(u) : "f"(hi), "f"(lo)); return u;
}
__device__ __forceinline__ float ex2(float x) {
    float y; asm("ex2.approx.ftz.f32 %0, %1;" : "=f"(y) : "f"(x)); return y;
}
__device__ __forceinline__ void mma_tf32(float c[4], const unsigned a[4],
                                         unsigned b0, unsigned b1) {
    asm("mma.sync.aligned.m16n8k8.row.col.f32.tf32.tf32.f32 "
        "{%0,%1,%2,%3}, {%4,%5,%6,%7}, {%8,%9}, {%0,%1,%2,%3};"
        : "+f"(c[0]), "+f"(c[1]), "+f"(c[2]), "+f"(c[3])
        : "r"(a[0]), "r"(a[1]), "r"(a[2]), "r"(a[3]), "r"(b0), "r"(b1));
}
__device__ __forceinline__ void mma_f16(float c[4], unsigned a0, unsigned a1,
                                        unsigned a2, unsigned a3,
                                        unsigned b0, unsigned b1) {
    asm("mma.sync.aligned.m16n8k16.row.col.f32.f16.f16.f32 "
        "{%0,%1,%2,%3}, {%4,%5,%6,%7}, {%8,%9}, {%0,%1,%2,%3};"
        : "+f"(c[0]), "+f"(c[1]), "+f"(c[2]), "+f"(c[3])
        : "r"(a0), "r"(a1), "r"(a2), "r"(a3), "r"(b0), "r"(b1));
}

__global__ __launch_bounds__(256)
void attn_mma_kernel(const float* __restrict__ QKV, float* __restrict__ O) {
    const int h    = blockIdx.y;
    const int warp = threadIdx.x >> 5;
    const int lane = threadIdx.x & 31;
    const int g    = lane >> 2;
    const int t    = lane & 3;
    const int q0   = blockIdx.x * 128 + warp * 16;

    __shared__ unsigned Ks[64][17];
    __shared__ float    Vs[64][17];

    const float qscale = 0.25f * 1.4426950408889634f;

    unsigned qa[2][4];
    {
        const float* Qb = QKV + h * HDIM;
        #pragma unroll
        for (int kk = 0; kk < 2; kk++) {
            qa[kk][0] = cvt_tf32(Qb[(q0 + g)     * 384 + kk * 8 + t]     * qscale);
            qa[kk][1] = cvt_tf32(Qb[(q0 + g + 8) * 384 + kk * 8 + t]     * qscale);
            qa[kk][2] = cvt_tf32(Qb[(q0 + g)     * 384 + kk * 8 + t + 4] * qscale);
            qa[kk][3] = cvt_tf32(Qb[(q0 + g + 8) * 384 + kk * 8 + t + 4] * qscale);
        }
    }

    float o[2][4];
    #pragma unroll
    for (int dt = 0; dt < 2; dt++)
        #pragma unroll
        for (int i = 0; i < 4; i++) o[dt][i] = 0.0f;
    float l0 = 0.0f, l1 = 0.0f;

    for (int k0 = 0; k0 < NN; k0 += 64) {
        __syncthreads();
        {
            int key = threadIdx.x & 63;
            int dh  = (threadIdx.x >> 6) * 4;
            const float* kb = QKV + (k0 + key) * 384 + FF + h * HDIM + dh;
            float4 kv = *(const float4*)kb;
            float4 vv = *(const float4*)(kb + FF);
            Ks[key][dh + 0] = cvt_tf32(kv.x);
            Ks[key][dh + 1] = cvt_tf32(kv.y);
            Ks[key][dh + 2] = cvt_tf32(kv.z);
            Ks[key][dh + 3] = cvt_tf32(kv.w);
            Vs[key][dh + 0] = vv.x;
            Vs[key][dh + 1] = vv.y;
            Vs[key][dh + 2] = vv.z;
            Vs[key][dh + 3] = vv.w;
        }
        __syncthreads();

        float c[8][4];
        #pragma unroll
        for (int j = 0; j < 8; j++) {
            c[j][0] = c[j][1] = c[j][2] = c[j][3] = 0.0f;
            #pragma unroll
            for (int kk = 0; kk < 2; kk++) {
                unsigned b0 = Ks[j * 8 + g][kk * 8 + t];
                unsigned b1 = Ks[j * 8 + g][kk * 8 + t + 4];
                mma_tf32(c[j], qa[kk], b0, b1);
            }
        }

        #pragma unroll
        for (int j = 0; j < 8; j++) {
            c[j][0] = ex2(c[j][0] - 8.0f);
            c[j][1] = ex2(c[j][1] - 8.0f);
            c[j][2] = ex2(c[j][2] - 8.0f);
            c[j][3] = ex2(c[j][3] - 8.0f);
            l0 += c[j][0] + c[j][1];
            l1 += c[j][2] + c[j][3];
        }

        #pragma unroll
        for (int kt = 0; kt < 4; kt++) {
            unsigned a0 = f16x2_hl(c[2 * kt][1],     c[2 * kt][0]);
            unsigned a1 = f16x2_hl(c[2 * kt][3],     c[2 * kt][2]);
            unsigned a2 = f16x2_hl(c[2 * kt + 1][1], c[2 * kt + 1][0]);
            unsigned a3 = f16x2_hl(c[2 * kt + 1][3], c[2 * kt + 1][2]);
            int kb = kt * 16;
            #pragma unroll
            for (int dt = 0; dt < 2; dt++) {
                int d = dt * 8 + g;
                unsigned b0 = f16x2_hl(Vs[kb + 2 * t + 1][d], Vs[kb + 2 * t][d]);
                unsigned b1 = f16x2_hl(Vs[kb + 2 * t + 9][d], Vs[kb + 2 * t + 8][d]);
                mma_f16(o[dt], a0, a1, a2, a3, b0, b1);
            }
        }
    }

    l0 += __shfl_xor_sync(0xffffffffu, l0, 1);
    l0 += __shfl_xor_sync(0xffffffffu, l0, 2);
    l1 += __shfl_xor_sync(0xffffffffu, l1, 1);
    l1 += __shfl_xor_sync(0xffffffffu, l1, 2);
    float inv0 = 1.0f / l0;
    float inv1 = 1.0f / l1;

    #pragma unroll
    for (int dt = 0; dt < 2; dt++) {
        int col = h * HDIM + dt * 8 + 2 * t;
        float2 v0 = make_float2(o[dt][0] * inv0, o[dt][1] * inv0);
        float2 v1 = make_float2(o[dt][2] * inv1, o[dt][3] * inv1);
        *(float2*)(O + (q0 + g)     * FF + col) = v0;
        *(float2*)(O + (q0 + g + 8) * FF + col) = v1;
    }
}

// ---------------- launch ----------------
extern "C" void kernel_launch(void* const* d_in, const int* in_sizes, int n_in,
                              void* d_out, int out_size) {
    const float* x          = (const float*)d_in[0];
    const int*   edge_index = (const int*)  d_in[1];
    const float* W1         = (const float*)d_in[2];
    const float* b1         = (const float*)d_in[3];
    const float* W2         = (const float*)d_in[4];
    const float* b2         = (const float*)d_in[5];
    const float* W3         = (const float*)d_in[6];
    const float* b3         = (const float*)d_in[7];
    const float* in_w       = (const float*)d_in[8];
    const float* in_b       = (const float*)d_in[9];
    const float* out_w      = (const float*)d_in[10];
    const float* out_b      = (const float*)d_in[11];
    const float* proj_w     = (const float*)d_in[12];
    const float* proj_b     = (const float*)d_in[13];
    float* out = (float*)d_out;

    const int* row = edge_index;
    const int* col = edge_index + EE;

    float *H, *G, *G2, *QKV, *O, *TF, *GNN, *dinv;
    int *cnt, *off, *cur, *srow;
    cudaGetSymbolAddress((void**)&H,    g_H);
    cudaGetSymbolAddress((void**)&G,    g_G);
    cudaGetSymbolAddress((void**)&G2,   g_G2);
    cudaGetSymbolAddress((void**)&QKV,  g_QKV);
    cudaGetSymbolAddress((void**)&O,    g_O);
    cudaGetSymbolAddress((void**)&TF,   g_TF);
    cudaGetSymbolAddress((void**)&GNN,  g_GNN);
    cudaGetSymbolAddress((void**)&dinv, g_dinv);
    cudaGetSymbolAddress((void**)&cnt,  g_count);
    cudaGetSymbolAddress((void**)&off,  g_off);
    cudaGetSymbolAddress((void**)&cur,  g_cur);
    cudaGetSymbolAddress((void**)&srow, g_srow);

    // ---- CSR build ----
    zero_count_kernel<<<(NN + 255) / 256, 256>>>(cnt);
    hist_kernel<<<(EE + 255) / 256, 256>>>(col, cnt);
    scan_kernel<<<1, 1024>>>(cnt, off, cur, dinv);
    reorder_kernel<<<(EE + 255) / 256, 256>>>(row, col, cur, srow);

    // ---- GCN conv 1: H = x@W1 ; G = relu(gather) ----
    pgemm_kernel<64, 32, false, false, false, false>
        <<<dim3(HID / 32, NN / 64), 256>>>(x, W1, nullptr, nullptr, H, NN, HID, FF);
    gather_kernel<<<NN / 8, 256>>>(H, srow, off, dinv, b1, G);

    // ---- GCN conv 2: H = G@W2 ; G2 = relu(gather) ----
    pgemm_kernel<64, 32, false, false, false, false>
        <<<dim3(HID / 32, NN / 64), 256>>>(G, W2, nullptr, nullptr, H, NN, HID, HID);
    gather_kernel<<<NN / 8, 256>>>(H, srow, off, dinv, b2, G2);

    // ---- GNN head: GNN = G2 @ W3 + b3 ----
    pgemm_kernel<32, 32, false, true, false, false>
        <<<dim3(CC / 32, NN / 32), 256>>>(G2, W3, b3, nullptr, GNN, NN, CC, HID);

    // ---- Transformer branch ----
    pgemm_kernel<64, 64, true, true, false, false>
        <<<dim3(3 * FF / 64, NN / 64), 256>>>(x, in_w, in_b, nullptr, QKV, NN, 3 * FF, FF);
    attn_mma_kernel<<<dim3(NN / 128, HEADS), 256>>>(QKV, O);
    pgemm_kernel<64, 32, true, true, false, false>
        <<<dim3(FF / 32, NN / 64), 256>>>(O, out_w, out_b, nullptr, TF, NN, FF, FF);
    // out = relu(TF @ proj_w + proj_b + GNN)
    pgemm_kernel<32, 32, false, true, true, true>
        <<<dim3(CC / 32, NN / 32), 256>>>(TF, proj_w, proj_b, GNN, out, NN, CC, FF);
}